// round 13
// baseline (speedup 1.0000x reference)
#include <cuda_runtime.h>
#include <cuda_bf16.h>
#include <cuda_fp16.h>
#include <cstdint>
#include <math.h>

#define SEQ     8192
#define BATCH   4
#define NH      8
#define HD      64
#define BHN     (BATCH*NH)      // 32
#define EMB     512
#define MTOT    (BATCH*SEQ)     // 32768
#define NCHUNK  16
#define CHUNK   (SEQ/NCHUNK)    // 512

// =================== baseline-PTX helpers (valid on .target sm_103) =======
__device__ __forceinline__ uint32_t smem_u32(const void* p) {
    uint32_t a;
    asm("{ .reg .u64 tmp; cvta.to.shared.u64 tmp, %1; cvt.u32.u64 %0, tmp; }"
        : "=r"(a) : "l"(p));
    return a;
}
#define SMEM_SWIZZLE_128B(off) ((off) ^ (((off) >> 3) & 0x70))

#define CP_ASYNC16(dst, src) \
    asm volatile("cp.async.cg.shared.global [%0], [%1], 16;" \
        :: "r"(dst), "l"(src) : "memory")
#define CP_COMMIT() asm volatile("cp.async.commit_group;" ::: "memory")
#define CP_WAIT1()  asm volatile("cp.async.wait_group 1;" ::: "memory")
#define CP_WAIT0()  asm volatile("cp.async.wait_group 0;" ::: "memory")

__device__ __forceinline__ void ldsm4(uint32_t& r0, uint32_t& r1,
                                      uint32_t& r2, uint32_t& r3, uint32_t addr) {
    asm volatile("ldmatrix.sync.aligned.m8n8.x4.shared.b16 {%0,%1,%2,%3}, [%4];"
        : "=r"(r0), "=r"(r1), "=r"(r2), "=r"(r3) : "r"(addr));
}
// fp16 MMA
__device__ __forceinline__ void mma16816h(float* c,
    uint32_t a0, uint32_t a1, uint32_t a2, uint32_t a3,
    uint32_t b0, uint32_t b1) {
    asm volatile("mma.sync.aligned.m16n8k16.row.col.f32.f16.f16.f32 "
        "{%0,%1,%2,%3}, {%4,%5,%6,%7}, {%8,%9}, {%0,%1,%2,%3};"
        : "+f"(c[0]), "+f"(c[1]), "+f"(c[2]), "+f"(c[3])
        : "r"(a0), "r"(a1), "r"(a2), "r"(a3), "r"(b0), "r"(b1));
}

// ---------------- scratch (device globals; allocation is forbidden) -------
__device__ __half g_q16[(size_t)BHN*SEQ*HD];    // [bh][s][d]
__device__ __half g_k16[(size_t)BHN*SEQ*HD];
__device__ __half g_vT16[(size_t)BHN*HD*SEQ];   // [bh][d][s]
__device__ __half g_x16[(size_t)MTOT*EMB];      // fp16 x
__device__ __half g_af[(size_t)MTOT*EMB];       // fp16 attn (merged heads)
__device__ __half g_w16[4*512*512];             // fp16 W^T [mat][n][k]
__device__ float g_qland[BHN*64*64];
__device__ float g_kland[BHN*64*64];
__device__ __half g_ql16[BHN*64*64];
__device__ __half g_kl16[BHN*64*64];
__device__ __half g_MfT16[BHN*64*64];           // [bh][d][l]
__device__ float g_K2[BHN*64*64];
__device__ float g_Vinv[BHN*64*64];
__device__ float g_Gpart[(size_t)BHN*NCHUNK*64*64];
__device__ float g_Mpart[BHN*NCHUNK*64];
__device__ float g_Lpart[BHN*NCHUNK*64];
__device__ int   g_denom_i;

// =================== split kernels (fp32 -> fp16) =========================
__global__ __launch_bounds__(256) void split_x(const float* __restrict__ x)
{
    size_t i = (size_t)blockIdx.x * 256 + threadIdx.x;   // float4 index
    float4 v = ((const float4*)x)[i];
    __half2 h0 = __floats2half2_rn(v.x, v.y);
    __half2 h1 = __floats2half2_rn(v.z, v.w);
    uint2 u; u.x = *(uint32_t*)&h0; u.y = *(uint32_t*)&h1;
    ((uint2*)g_x16)[i] = u;
}

__global__ __launch_bounds__(256) void split_w(
    const float* __restrict__ Wq, const float* __restrict__ Wk,
    const float* __restrict__ Wv, const float* __restrict__ Wo)
{
    if (blockIdx.x == 0 && blockIdx.y == 0 && threadIdx.x == 0) g_denom_i = 0;
    const float* src = (blockIdx.y == 0) ? Wq : (blockIdx.y == 1) ? Wk
                     : (blockIdx.y == 2) ? Wv : Wo;
    int n = blockIdx.x;
    size_t obase = ((size_t)blockIdx.y * 512 + n) * 512;
    for (int k = threadIdx.x; k < 512; k += 256) {
        g_w16[obase + k] = __float2half(src[(size_t)k * 512 + n]);
    }
}

// =================== single-term fp16 warp-MMA GEMM =======================
#define SUB_SZ   16384
#define STAGE_SZ (2*SUB_SZ)          // 32KB: A, B (fp16)
#define NSTAGE   3
#define SMEM_TOT (NSTAGE*STAGE_SZ)   // 98304

// mode 0: QKV fused (blockIdx.z = 0:q, 1:k, 2:v); mode 1: output GEMM.
__global__ __launch_bounds__(256, 2) void tc_gemm(
    const float* __restrict__ b0, const float* __restrict__ b1,
    const float* __restrict__ b2, float* __restrict__ out_ext, int mode)
{
    extern __shared__ char smem[];
    uint32_t sb = smem_u32(smem);
    int t = threadIdx.x;
    int wid = t >> 5, lane = t & 31;
    int wm = wid & 3, wn = wid >> 2;   // warp grid 4(M) x 2(N)
    int rowStart = blockIdx.y * 128;
    int colStart = blockIdx.x * 128;

    int out_sel, widx;
    const float* bias;
    float scale;
    if (mode == 0) {
        out_sel = blockIdx.z; widx = blockIdx.z;
        bias = (out_sel == 0) ? b0 : (out_sel == 1) ? b1 : b2;
        scale = (out_sel == 2) ? 1.0f : 0.35355339059327373f;
    } else {
        out_sel = 3; widx = 3; bias = b0; scale = 1.0f;
    }

    const __half* Ag = (mode ? g_af : g_x16) + (size_t)rowStart * 512;
    const __half* Bg = g_w16 + ((size_t)widx * 512 + colStart) * 512;

    float acc[2][8][4];
    #pragma unroll
    for (int mt = 0; mt < 2; mt++)
        #pragma unroll
        for (int nt = 0; nt < 8; nt++)
            #pragma unroll
            for (int q = 0; q < 4; q++) acc[mt][nt][q] = 0.f;

    auto issue = [&](int kt, int buf) {
        const __half* srcs[2] = { Ag + kt * 64, Bg + kt * 64 };
        #pragma unroll
        for (int s2 = 0; s2 < 2; s2++) {
            const char* src = (const char*)srcs[s2];
            uint32_t dstb = sb + buf * STAGE_SZ + s2 * SUB_SZ;
            #pragma unroll
            for (int r = 0; r < 4; r++) {
                int ci = r * 256 + t;
                int row = ci >> 3, c16 = ci & 7;
                const char* s = src + (size_t)row * 1024 + c16 * 16;
                uint32_t d = dstb + SMEM_SWIZZLE_128B(row * 128 + c16 * 16);
                CP_ASYNC16(d, s);
            }
        }
        CP_COMMIT();
    };

    issue(0, 0);
    issue(1, 1);
    for (int kt = 0; kt < 8; kt++) {
        if (kt == 7) { CP_WAIT0(); } else { CP_WAIT1(); }
        __syncthreads();
        if (kt + 2 < 8) issue(kt + 2, (kt + 2) % NSTAGE);

        uint32_t sbb = sb + (kt % NSTAGE) * STAGE_SZ;
        uint32_t aB = sbb, bB = sbb + SUB_SZ;

        #pragma unroll
        for (int ks = 0; ks < 4; ks++) {
            uint32_t a[2][4], b[4][4];
            #pragma unroll
            for (int mt = 0; mt < 2; mt++) {
                int row  = wm * 32 + mt * 16 + (lane & 15);
                int boff = ks * 32 + ((lane >> 4) << 4);
                uint32_t off = SMEM_SWIZZLE_128B(row * 128 + boff);
                ldsm4(a[mt][0], a[mt][1], a[mt][2], a[mt][3], aB + off);
            }
            #pragma unroll
            for (int np = 0; np < 4; np++) {
                int g = lane >> 3, l = lane & 7;
                int row  = wn * 64 + np * 16 + ((g >> 1) << 3) + l;
                int boff = ks * 32 + ((g & 1) << 4);
                uint32_t off = SMEM_SWIZZLE_128B(row * 128 + boff);
                ldsm4(b[np][0], b[np][1], b[np][2], b[np][3], bB + off);
            }
            #pragma unroll
            for (int mt = 0; mt < 2; mt++)
                #pragma unroll
                for (int np = 0; np < 4; np++) {
                    mma16816h(acc[mt][2 * np],     a[mt][0], a[mt][1], a[mt][2], a[mt][3],
                              b[np][0], b[np][1]);
                    mma16816h(acc[mt][2 * np + 1], a[mt][0], a[mt][1], a[mt][2], a[mt][3],
                              b[np][2], b[np][3]);
                }
        }
    }
    __syncthreads();

    // ---- epilogue
    int qrow = lane >> 2, qcol = (lane & 3) * 2;
    #pragma unroll
    for (int mt = 0; mt < 2; mt++) {
        #pragma unroll
        for (int nt = 0; nt < 8; nt++) {
            int col = colStart + wn * 64 + nt * 8 + qcol;
            float bb0 = bias[col], bb1 = bias[col + 1];
            #pragma unroll
            for (int hh = 0; hh < 2; hh++) {
                int row = rowStart + wm * 32 + mt * 16 + qrow + hh * 8;
                float fx = (acc[mt][nt][2 * hh + 0] + bb0) * scale;
                float fy = (acc[mt][nt][2 * hh + 1] + bb1) * scale;
                int b_ = row >> 13, s = row & 8191;
                int h = col >> 6, d = col & 63;
                if (out_sel <= 1) {          // q or k: fp16, head-split
                    size_t o = (((size_t)(b_ * NH + h) * SEQ + s) << 6) + d;
                    __half2 hv = __floats2half2_rn(fx, fy);
                    *(uint32_t*)((out_sel == 0 ? g_q16 : g_k16) + o) = *(uint32_t*)&hv;
                } else if (out_sel == 2) {   // v: transposed fp16 [bh][d][s]
                    size_t base = ((size_t)(b_ * NH + h) * 64 + d) * SEQ + s;
                    g_vT16[base]       = __float2half(fx);
                    g_vT16[base + SEQ] = __float2half(fy);
                } else {                     // output: fp32
                    float2 f; f.x = fx; f.y = fy;
                    *(float2*)(out_ext + (size_t)row * 512 + col) = f;
                }
            }
        }
    }

    // ---- fused landmark means for q/k: this M-tile == one 128-row segment
    if (out_sel <= 1) {
        float* red = (float*)smem;   // 128 floats (stage smem is dead now)
        if (t < 128) red[t] = 0.f;
        __syncthreads();
        #pragma unroll
        for (int nt = 0; nt < 8; nt++) {
            float sx = 0.f, sy = 0.f;
            #pragma unroll
            for (int mt = 0; mt < 2; mt++) {
                sx += acc[mt][nt][0] + acc[mt][nt][2];
                sy += acc[mt][nt][1] + acc[mt][nt][3];
            }
            sx += __shfl_xor_sync(0xFFFFFFFF, sx, 4);
            sx += __shfl_xor_sync(0xFFFFFFFF, sx, 8);
            sx += __shfl_xor_sync(0xFFFFFFFF, sx, 16);
            sy += __shfl_xor_sync(0xFFFFFFFF, sy, 4);
            sy += __shfl_xor_sync(0xFFFFFFFF, sy, 8);
            sy += __shfl_xor_sync(0xFFFFFFFF, sy, 16);
            if ((lane >> 2) == 0) {
                int colr = wn * 64 + nt * 8 + qcol;
                atomicAdd(&red[colr],     sx);
                atomicAdd(&red[colr + 1], sy);
            }
        }
        __syncthreads();
        if (t < 128) {
            int col = colStart + t;
            float mean = (red[t] * (1.f / 128.f) + bias[col]) * scale;
            int b_ = rowStart >> 13;
            int l  = (rowStart & 8191) >> 7;
            int h  = col >> 6, d = col & 63;
            int idx = ((b_ * NH + h) * 64 + l) * 64 + d;
            if (out_sel == 0) {
                g_qland[idx] = mean; g_ql16[idx] = __float2half(mean);
            } else {
                g_kland[idx] = mean; g_kl16[idx] = __float2half(mean);
            }
        }
    }
}

// ---------------- 64x64 matmul helper for 512 threads (2x4 per thread) ----
// ty in [0,32): rows ty*2..+1 ; tx in [0,16): cols tx*4..+3
__device__ __forceinline__ void mm64_2x4(float cr[2][4],
    const float* __restrict__ X, int px,
    const float* __restrict__ Y, int py, int tx, int ty)
{
    #pragma unroll 16
    for (int k = 0; k < 64; k++) {
        float a_[2], b_[4];
        #pragma unroll
        for (int ii = 0; ii < 2; ii++) a_[ii] = X[(ty * 2 + ii) * px + k];
        #pragma unroll
        for (int jj = 0; jj < 4; jj++) b_[jj] = Y[k * py + tx * 4 + jj];
        #pragma unroll
        for (int ii = 0; ii < 2; ii++)
            #pragma unroll
            for (int jj = 0; jj < 4; jj++)
                cr[ii][jj] += a_[ii] * b_[jj];
    }
}

// ---------------- kernel_2 softmax + global colsum max (512 thr) ----------
__global__ __launch_bounds__(512) void k2_softmax()
{
    int bh = blockIdx.x, t = threadIdx.x;
    __shared__ float qL[4096];
    __shared__ float kT[64 * 65];
    __shared__ float S[64 * 65];
    const float* qlb = g_qland + bh * 4096;
    const float* klb = g_kland + bh * 4096;
    for (int idx = t; idx < 4096; idx += 512) {
        qL[idx] = qlb[idx];
        int j = idx >> 6, d = idx & 63;
        kT[d * 65 + j] = klb[idx];
    }
    __syncthreads();
    int tx = t & 15, ty = t >> 4;
    float cr[2][4] = {};
    mm64_2x4(cr, qL, 64, kT, 65, tx, ty);
    #pragma unroll
    for (int ii = 0; ii < 2; ii++)
        #pragma unroll
        for (int jj = 0; jj < 4; jj++)
            S[(ty * 2 + ii) * 65 + tx * 4 + jj] = cr[ii][jj];
    __syncthreads();
    // ---- softmax: 8 threads per row, 8 cols per thread
    {
        int row = t >> 3, c8 = (t & 7) * 8;
        float v[8], mx = -1e30f;
        #pragma unroll
        for (int j = 0; j < 8; j++) { v[j] = S[row * 65 + c8 + j]; mx = fmaxf(mx, v[j]); }
        mx = fmaxf(mx, __shfl_xor_sync(0xFFFFFFFF, mx, 1));
        mx = fmaxf(mx, __shfl_xor_sync(0xFFFFFFFF, mx, 2));
        mx = fmaxf(mx, __shfl_xor_sync(0xFFFFFFFF, mx, 4));
        float sum = 0.f;
        #pragma unroll
        for (int j = 0; j < 8; j++) { v[j] = __expf(v[j] - mx); sum += v[j]; }
        sum += __shfl_xor_sync(0xFFFFFFFF, sum, 1);
        sum += __shfl_xor_sync(0xFFFFFFFF, sum, 2);
        sum += __shfl_xor_sync(0xFFFFFFFF, sum, 4);
        float inv = 1.f / sum;
        #pragma unroll
        for (int j = 0; j < 8; j++) S[row * 65 + c8 + j] = v[j] * inv;
    }
    __syncthreads();
    // ---- column sums (8 threads per column), global max via atomic
    {
        int col = t >> 3, r8 = (t & 7) * 8;
        float cs = 0.f;
        #pragma unroll
        for (int r = 0; r < 8; r++) cs += S[(r8 + r) * 65 + col];
        cs += __shfl_xor_sync(0xFFFFFFFF, cs, 1);
        cs += __shfl_xor_sync(0xFFFFFFFF, cs, 2);
        cs += __shfl_xor_sync(0xFFFFFFFF, cs, 4);
        if ((t & 7) == 0) atomicMax(&g_denom_i, __float_as_int(cs));
    }
    float* ko = g_K2 + bh * 4096;
    for (int idx = t; idx < 4096; idx += 512) {
        int i = idx >> 6, j = idx & 63;
        ko[idx] = S[i * 65 + j];
    }
}

// ---------------- Newton-Schulz pseudo-inverse (512 thr) ------------------
__global__ __launch_bounds__(512) void newton_inv()
{
    int bh = blockIdx.x, t = threadIdx.x;
    extern __shared__ float sm[];
    float* Kd = sm;
    float* V  = Kd + 4096;
    float* C  = V  + 4096;
    float* M1 = C  + 4096;
    float* M2 = M1 + 4096;
    const float* kb = g_K2 + bh * 4096;
    for (int idx = t; idx < 4096; idx += 512) Kd[idx] = kb[idx];
    float denom = __int_as_float(g_denom_i);
    __syncthreads();
    float inv = 1.f / denom;
    for (int idx = t; idx < 4096; idx += 512) {
        int i = idx >> 6, j = idx & 63;
        V[idx] = Kd[j * 64 + i] * inv;
    }
    __syncthreads();
    int tx = t & 15, ty = t >> 4;
    for (int it = 0; it < 6; it++) {
        { float cr[2][4] = {}; mm64_2x4(cr, Kd, 64, V, 64, tx, ty);
          #pragma unroll
          for (int ii = 0; ii < 2; ii++) for (int jj = 0; jj < 4; jj++)
              C[(ty*2+ii)*64 + tx*4+jj] = cr[ii][jj]; }
        __syncthreads();
        { float cr[2][4] = {}; mm64_2x4(cr, C, 64, C, 64, tx, ty);
          #pragma unroll
          for (int ii = 0; ii < 2; ii++) for (int jj = 0; jj < 4; jj++) {
              int o = (ty*2+ii)*64 + tx*4+jj;
              M1[o] = 7.f * C[o] - cr[ii][jj]; } }
        __syncthreads();
        { float cr[2][4] = {}; mm64_2x4(cr, C, 64, M1, 64, tx, ty);
          #pragma unroll
          for (int ii = 0; ii < 2; ii++) for (int jj = 0; jj < 4; jj++) {
              int o = (ty*2+ii)*64 + tx*4+jj;
              M2[o] = 15.f * C[o] - cr[ii][jj]; } }
        __syncthreads();
        { float cr[2][4] = {}; mm64_2x4(cr, V, 64, M2, 64, tx, ty);
          #pragma unroll
          for (int ii = 0; ii < 2; ii++) for (int jj = 0; jj < 4; jj++) {
              int o = (ty*2+ii)*64 + tx*4+jj;
              M1[o] = 3.25f * V[o] - 0.25f * cr[ii][jj]; } }
        __syncthreads();
        for (int idx = t; idx < 4096; idx += 512) V[idx] = M1[idx];
        __syncthreads();
    }
    float* vo = g_Vinv + bh * 4096;
    for (int idx = t; idx < 4096; idx += 512) vo[idx] = V[idx];
}

// ---------------- flash kernel_3 @ v : fp16 MMA version -------------------
#define FL_Q    0
#define FL_BUF  8192           // buf b at FL_BUF + b*16384; sub: k16, vT16 (8KB each)
#define FL_SMEM 40960

__global__ __launch_bounds__(128, 3) void flash_k3v_mma()
{
    extern __shared__ char fs[];
    uint32_t sb = smem_u32(fs);
    const int t = threadIdx.x, w = t >> 5, lane = t & 31;
    const int chunk = blockIdx.x, bhead = blockIdx.y;

    {
        const __half* qh = g_ql16 + bhead * 4096;
        #pragma unroll
        for (int i = 0; i < 4; i++) {
            int ci = i * 128 + t;
            int row = ci >> 3, c16 = ci & 7;
            uint32_t sw = SMEM_SWIZZLE_128B(row * 128 + c16 * 16);
            *(uint4*)(fs + FL_Q + sw) = *(const uint4*)(qh + row * 64 + c16 * 8);
        }
    }
    __syncthreads();

    uint32_t ah[4][4];
    #pragma unroll
    for (int ks = 0; ks < 4; ks++) {
        int row  = w * 16 + (lane & 15);
        int boff = ks * 32 + ((lane >> 4) << 4);
        uint32_t off = SMEM_SWIZZLE_128B(row * 128 + boff);
        ldsm4(ah[ks][0], ah[ks][1], ah[ks][2], ah[ks][3], sb + FL_Q + off);
    }

    auto issue = [&](int sub, int b) {
        int s0 = chunk * CHUNK + sub * 64;
        const __half* srcs[2] = {
            g_k16  + ((size_t)bhead * SEQ + s0) * 64,
            g_vT16 + ((size_t)bhead * 64) * SEQ + s0 };
        #pragma unroll
        for (int s2 = 0; s2 < 2; s2++) {
            size_t rs = (s2 == 0) ? 64 : SEQ;
            const char* src = (const char*)srcs[s2];
            uint32_t dstb = sb + FL_BUF + b * 16384 + s2 * 8192;
            #pragma unroll
            for (int r = 0; r < 4; r++) {
                int ci = r * 128 + t;
                int row = ci >> 3, c16 = ci & 7;
                const char* s = src + (row * rs + c16 * 8) * 2;
                CP_ASYNC16(dstb + SMEM_SWIZZLE_128B(row * 128 + c16 * 16), s);
            }
        }
        CP_COMMIT();
    };

    float mA = -1e30f, mB = -1e30f, lA = 0.f, lB = 0.f;
    float o[8][4];
    #pragma unroll
    for (int nt = 0; nt < 8; nt++)
        #pragma unroll
        for (int q = 0; q < 4; q++) o[nt][q] = 0.f;

    issue(0, 0);
    for (int sub = 0; sub < 8; sub++) {
        int buf = sub & 1;
        if (sub + 1 < 8) { issue(sub + 1, buf ^ 1); CP_WAIT1(); }
        else            { CP_WAIT0(); }
        __syncthreads();

        uint32_t khb = sb + FL_BUF + buf * 16384;
        uint32_t vhb = khb + 8192;

        float c[8][4];
        #pragma unroll
        for (int nt = 0; nt < 8; nt++)
            #pragma unroll
            for (int q = 0; q < 4; q++) c[nt][q] = 0.f;

        #pragma unroll
        for (int ks = 0; ks < 4; ks++) {
            #pragma unroll
            for (int np = 0; np < 4; np++) {
                int g = lane >> 3, l = lane & 7;
                int row  = np * 16 + ((g >> 1) << 3) + l;
                int boff = ks * 32 + ((g & 1) << 4);
                uint32_t off = SMEM_SWIZZLE_128B(row * 128 + boff);
                uint32_t kb[4];
                ldsm4(kb[0], kb[1], kb[2], kb[3], khb + off);
                mma16816h(c[2 * np],     ah[ks][0], ah[ks][1], ah[ks][2], ah[ks][3], kb[0], kb[1]);
                mma16816h(c[2 * np + 1], ah[ks][0], ah[ks][1], ah[ks][2], ah[ks][3], kb[2], kb[3]);
            }
        }

        float mxA = -1e30f, mxB = -1e30f;
        #pragma unroll
        for (int nt = 0; nt < 8; nt++) {
            mxA = fmaxf(mxA, fmaxf(c[nt][0], c[nt][1]));
            mxB = fmaxf(mxB, fmaxf(c[nt][2], c[nt][3]));
        }
        mxA = fmaxf(mxA, __shfl_xor_sync(0xFFFFFFFF, mxA, 1));
        mxA = fmaxf(mxA, __shfl_xor_sync(0xFFFFFFFF, mxA, 2));
        mxB = fmaxf(mxB, __shfl_xor_sync(0xFFFFFFFF, mxB, 1));
        mxB = fmaxf(mxB, __shfl_xor_sync(0xFFFFFFFF, mxB, 2));
        float mnA = fmaxf(mA, mxA), mnB = fmaxf(mB, mxB);
        float fA = __expf(mA - mnA), fB = __expf(mB - mnB);
        float sumA = 0.f, sumB = 0.f;
        #pragma unroll
        for (int nt = 0; nt < 8; nt++) {
            c[nt][0] = __expf(c[nt][0] - mnA); sumA += c[nt][0];
            c[nt][1] = __expf(c[nt][1] - mnA); sumA += c[nt][1];
            c[nt][2] = __expf(c[nt][2] - mnB); sumB += c[nt][2];
            c[nt][3] = __expf(c[nt][3] - mnB); sumB += c[nt][3];
        }
        sumA += __shfl_xor_sync(0xFFFFFFFF, sumA, 1);
        sumA += __shfl_xor_sync(0xFFFFFFFF, sumA, 2);
        sumB += __shfl_xor_sync(0xFFFFFFFF, sumB, 1);
        sumB += __shfl_xor_sync(0xFFFFFFFF, sumB, 2);
        lA = lA * fA + sumA; lB = lB * fB + sumB;
        mA = mnA; mB = mnB;
        #pragma unroll
        for (int nt = 0; nt < 8; nt++) {
            o[nt][0] *= fA; o[nt][1] *= fA;
            o[nt][2] *= fB; o[nt][3] *= fB;
        }

        #pragma unroll
        for (int kt = 0; kt < 4; kt++) {
            uint32_t pa[4];
            __half2 p0 = __floats2half2_rn(c[2*kt][0],   c[2*kt][1]);
            __half2 p1 = __floats2half2_rn(c[2*kt][2],   c[2*kt][3]);
            __half2 p2 = __floats2half2_rn(c[2*kt+1][0], c[2*kt+1][1]);
            __half2 p3 = __floats2half2_rn(c[2*kt+1][2], c[2*kt+1][3]);
            pa[0] = *(uint32_t*)&p0; pa[1] = *(uint32_t*)&p1;
            pa[2] = *(uint32_t*)&p2; pa[3] = *(uint32_t*)&p3;
            #pragma unroll
            for (int np = 0; np < 4; np++) {
                int g = lane >> 3, l = lane & 7;
                int row  = np * 16 + ((g >> 1) << 3) + l;
                int boff = kt * 32 + ((g & 1) << 4);
                uint32_t off = SMEM_SWIZZLE_128B(row * 128 + boff);
                uint32_t vh[4];
                ldsm4(vh[0], vh[1], vh[2], vh[3], vhb + off);
                mma16816h(o[2 * np],     pa[0], pa[1], pa[2], pa[3], vh[0], vh[1]);
                mma16816h(o[2 * np + 1], pa[0], pa[1], pa[2], pa[3], vh[2], vh[3]);
            }
        }
        __syncthreads();
    }

    float* gp = g_Gpart + (size_t)(bhead * NCHUNK + chunk) * 4096;
    int rA = w * 16 + (lane >> 2), rB = rA + 8;
    #pragma unroll
    for (int nt = 0; nt < 8; nt++) {
        int col = (nt >> 1) * 16 + (nt & 1) * 8 + (lane & 3) * 2;
        *(float2*)(gp + rA * 64 + col) = make_float2(o[nt][0], o[nt][1]);
        *(float2*)(gp + rB * 64 + col) = make_float2(o[nt][2], o[nt][3]);
    }
    if ((lane & 3) == 0) {
        int base = (bhead * NCHUNK + chunk) * 64;
        g_Mpart[base + rA] = mA; g_Mpart[base + rB] = mB;
        g_Lpart[base + rA] = lA; g_Lpart[base + rB] = lB;
    }
}

// ------- fused: merge partials -> G3v, then Mf = Vinv @ G3v (512 thr) -----
__global__ __launch_bounds__(512) void apply_inv()
{
    int bh = blockIdx.x, t = threadIdx.x;
    __shared__ float A[4096], B[4096];
    __shared__ float mrow[64], zinv[64];
    __shared__ float wgt[NCHUNK * 64];

    const float* va = g_Vinv + bh * 4096;
    for (int idx = t; idx < 4096; idx += 512) A[idx] = va[idx];

    if (t < 64) {
        float m = -1e30f;
        for (int c = 0; c < NCHUNK; c++)
            m = fmaxf(m, g_Mpart[(bh * NCHUNK + c) * 64 + t]);
        float z = 0.f;
        for (int c = 0; c < NCHUNK; c++)
            z += __expf(g_Mpart[(bh * NCHUNK + c) * 64 + t] - m) *
                 g_Lpart[(bh * NCHUNK + c) * 64 + t];
        mrow[t] = m; zinv[t] = 1.f / z;
    }
    __syncthreads();
    for (int idx = t; idx < NCHUNK * 64; idx += 512) {
        int c = idx >> 6, i = idx & 63;
        wgt[idx] = __expf(g_Mpart[(bh * NCHUNK + c) * 64 + i] - mrow[i]);
    }
    __syncthreads();
    for (int idx = t; idx < 4096; idx += 512) {
        int i = idx >> 6, d = idx & 63;
        float accv = 0.f;
        #pragma unroll 4
        for (int c = 0; c < NCHUNK; c++)
            accv += wgt[c * 64 + i] *
                    g_Gpart[((size_t)(bh * NCHUNK + c)) * 4096 + i * 64 + d];
        B[idx] = accv * zinv[i];
    }
    __syncthreads();

    int tx = t & 15, ty = t >> 4;
    float cr[2][4] = {};
    mm64_2x4(cr, A, 64, B, 64, tx, ty);
    #pragma unroll
    for (int ii = 0; ii < 2; ii++)
        #pragma unroll
        for (int jj = 0; jj < 4; jj++) {
            int i = ty * 2 + ii, j = tx * 4 + jj;
            g_MfT16[bh * 4096 + j * 64 + i] = __float2half(cr[ii][jj]);
        }
}

// ---------------- kernel_1 softmax + @Mf : fp16 MMA version ---------------
#define K1_Q    0
#define K1_K    8192
#define K1_M    16384
#define K1_SMEM 24576

__global__ __launch_bounds__(128, 4) void k1_apply_mma()
{
    extern __shared__ char fs[];
    uint32_t sb = smem_u32(fs);
    const int t = threadIdx.x, w = t >> 5, lane = t & 31;
    const int st = blockIdx.x, bhead = blockIdx.y;

    {
        const __half* srcs[3] = {
            g_q16 + ((size_t)bhead * SEQ + st * 64) * 64,
            g_kl16 + bhead * 4096,
            g_MfT16 + bhead * 4096 };
        #pragma unroll
        for (int s3 = 0; s3 < 3; s3++) {
            const __half* src = srcs[s3];
            int dstb = s3 * 8192;
            #pragma unroll
            for (int i = 0; i < 4; i++) {
                int ci = i * 128 + t;
                int row = ci >> 3, c16 = ci & 7;
                uint32_t sw = SMEM_SWIZZLE_128B(row * 128 + c16 * 16);
                *(uint4*)(fs + dstb + sw) = *(const uint4*)(src + row * 64 + c16 * 8);
            }
        }
    }
    __syncthreads();

    float c[8][4];
    #pragma unroll
    for (int nt = 0; nt < 8; nt++)
        #pragma unroll
        for (int q = 0; q < 4; q++) c[nt][q] = 0.f;

    #pragma unroll
    for (int ks = 0; ks < 4; ks++) {
        uint32_t a[4];
        {
            int row  = w * 16 + (lane & 15);
            int boff = ks * 32 + ((lane >> 4) << 4);
            uint32_t off = SMEM_SWIZZLE_128B(row * 128 + boff);
            ldsm4(a[0], a[1], a[2], a[3], sb + K1_Q + off);
        }
        #pragma unroll
        for (int np = 0; np < 4; np++) {
            int g = lane >> 3, l = lane & 7;
            int row  = np * 16 + ((g >> 1) << 3) + l;
            int boff = ks * 32 + ((g & 1) << 4);
            uint32_t off = SMEM_SWIZZLE_128B(row * 128 + boff);
            uint32_t kb[4];
            ldsm4(kb[0], kb[1], kb[2], kb[3], sb + K1_K + off);
            mma16816h(c[2 * np],     a[0], a[1], a[2], a[3], kb[0], kb[1]);
            mma16816h(c[2 * np + 1], a[0], a[1], a[2], a[3], kb[2], kb[3]);
        }
    }

    float mxA = -1e30f, mxB = -1e30f;
    #pragma unroll
    for (int nt = 0; nt < 8; nt++) {
        mxA = fmaxf(mxA, fmaxf(c[nt][0], c[nt][1]));
        mxB = fmaxf(mxB, fmaxf(c[nt][2], c[nt][3]));
    }
    mxA = fmaxf(mxA, __shfl_xor_sync(0xFFFFFFFF, mxA, 1));
    mxA = fmaxf(mxA, __shfl_xor_sync(0xFFFFFFFF, mxA, 2));
    mxB = fmaxf(mxB, __shfl_xor_sync(0xFFFFFFFF, mxB, 1));
    mxB = fmaxf(mxB, __shfl_xor_sync(0xFFFFFFFF, mxB, 2));
    float sumA = 0.f, sumB = 0.f;
    #pragma unroll
    for (int nt = 0; nt < 8; nt++) {
        c[nt][0] = __expf(c[nt][0] - mxA); sumA += c[nt][0];
        c[nt][1] = __expf(c[nt][1] - mxA); sumA += c[nt][1];
        c[nt][2] = __expf(c[nt][2] - mxB); sumB += c[nt][2];
        c[nt][3] = __expf(c[nt][3] - mxB); sumB += c[nt][3];
    }
    sumA += __shfl_xor_sync(0xFFFFFFFF, sumA, 1);
    sumA += __shfl_xor_sync(0xFFFFFFFF, sumA, 2);
    sumB += __shfl_xor_sync(0xFFFFFFFF, sumB, 1);
    sumB += __shfl_xor_sync(0xFFFFFFFF, sumB, 2);
    float iA = 1.f / sumA, iB = 1.f / sumB;
    #pragma unroll
    for (int nt = 0; nt < 8; nt++) {
        c[nt][0] *= iA; c[nt][1] *= iA;
        c[nt][2] *= iB; c[nt][3] *= iB;
    }

    float o[8][4];
    #pragma unroll
    for (int nt = 0; nt < 8; nt++)
        #pragma unroll
        for (int q = 0; q < 4; q++) o[nt][q] = 0.f;

    #pragma unroll
    for (int kt = 0; kt < 4; kt++) {
        uint32_t pa[4];
        __half2 p0 = __floats2half2_rn(c[2*kt][0],   c[2*kt][1]);
        __half2 p1 = __floats2half2_rn(c[2*kt][2],   c[2*kt][3]);
        __half2 p2 = __floats2half2_rn(c[2*kt+1][0], c[2*kt+1][1]);
        __half2 p3 = __floats2half2_rn(c[2*kt+1][2], c[2*kt+1][3]);
        pa[0] = *(uint32_t*)&p0; pa[1] = *(uint32_t*)&p1;
        pa[2] = *(uint32_t*)&p2; pa[3] = *(uint32_t*)&p3;
        #pragma unroll
        for (int np = 0; np < 4; np++) {
            int g = lane >> 3, l = lane & 7;
            int row  = np * 16 + ((g >> 1) << 3) + l;
            int boff = kt * 32 + ((g & 1) << 4);
            uint32_t off = SMEM_SWIZZLE_128B(row * 128 + boff);
            uint32_t mh[4];
            ldsm4(mh[0], mh[1], mh[2], mh[3], sb + K1_M + off);
            mma16816h(o[2 * np],     pa[0], pa[1], pa[2], pa[3], mh[0], mh[1]);
            mma16816h(o[2 * np + 1], pa[0], pa[1], pa[2], pa[3], mh[2], mh[3]);
        }
    }

    // ---- epilogue: write merged-head fp16 for the output GEMM
    int b_ = bhead >> 3, h = bhead & 7;
    int sA = st * 64 + w * 16 + (lane >> 2), sB = sA + 8;
    #pragma unroll
    for (int nt = 0; nt < 8; nt++) {
        int col = (nt >> 1) * 16 + (nt & 1) * 8 + (lane & 3) * 2;
        size_t oA = ((size_t)(b_ * SEQ + sA)) * 512 + h * 64 + col;
        __half2 hA = __floats2half2_rn(o[nt][0], o[nt][1]);
        *(uint32_t*)(g_af + oA) = *(uint32_t*)&hA;
        size_t oB = ((size_t)(b_ * SEQ + sB)) * 512 + h * 64 + col;
        __half2 hB = __floats2half2_rn(o[nt][2], o[nt][3]);
        *(uint32_t*)(g_af + oB) = *(uint32_t*)&hB;
    }
}

// ---------------- launch --------------------------------------------------
extern "C" void kernel_launch(void* const* d_in, const int* in_sizes, int n_in,
                              void* d_out, int out_size)
{
    const float* x  = (const float*)d_in[0];
    const float* Wq = (const float*)d_in[1];
    const float* bq = (const float*)d_in[2];
    const float* Wk = (const float*)d_in[3];
    const float* bk = (const float*)d_in[4];
    const float* Wv = (const float*)d_in[5];
    const float* bv = (const float*)d_in[6];
    const float* Wo = (const float*)d_in[7];
    const float* bo = (const float*)d_in[8];
    float* out = (float*)d_out;

    cudaFuncSetAttribute(tc_gemm,       cudaFuncAttributeMaxDynamicSharedMemorySize, SMEM_TOT);
    cudaFuncSetAttribute(newton_inv,    cudaFuncAttributeMaxDynamicSharedMemorySize, 5 * 4096 * 4);
    cudaFuncSetAttribute(flash_k3v_mma, cudaFuncAttributeMaxDynamicSharedMemorySize, FL_SMEM);
    cudaFuncSetAttribute(k1_apply_mma,  cudaFuncAttributeMaxDynamicSharedMemorySize, K1_SMEM);

    split_w<<<dim3(512, 4), 256>>>(Wq, Wk, Wv, Wo);
    split_x<<<(MTOT * EMB / 4) / 256, 256>>>(x);

    tc_gemm<<<dim3(4, 256, 3), 256, SMEM_TOT>>>(bq, bk, bv, nullptr, 0); // QKV + landmarks

    k2_softmax<<<BHN, 512>>>();
    flash_k3v_mma<<<dim3(NCHUNK, BHN), 128, FL_SMEM>>>();
    newton_inv<<<BHN, 512, 5 * 4096 * 4>>>();
    apply_inv<<<BHN, 512>>>();
    k1_apply_mma<<<dim3(SEQ / 64, BHN), 128, K1_SMEM>>>();

    tc_gemm<<<dim3(4, 256, 1), 256, SMEM_TOT>>>(bo, nullptr, nullptr, out, 1);
}

// round 15
// speedup vs baseline: 1.0526x; 1.0526x over previous
#include <cuda_runtime.h>
#include <cuda_bf16.h>
#include <cuda_fp16.h>
#include <cstdint>
#include <math.h>

#define SEQ     8192
#define BATCH   4
#define NH      8
#define HD      64
#define BHN     (BATCH*NH)      // 32
#define EMB     512
#define MTOT    (BATCH*SEQ)     // 32768
#define NCHUNK  16
#define CHUNK   (SEQ/NCHUNK)    // 512

// =================== baseline-PTX helpers (valid on .target sm_103) =======
__device__ __forceinline__ uint32_t smem_u32(const void* p) {
    uint32_t a;
    asm("{ .reg .u64 tmp; cvta.to.shared.u64 tmp, %1; cvt.u32.u64 %0, tmp; }"
        : "=r"(a) : "l"(p));
    return a;
}
#define SMEM_SWIZZLE_128B(off) ((off) ^ (((off) >> 3) & 0x70))

#define CP_ASYNC16(dst, src) \
    asm volatile("cp.async.cg.shared.global [%0], [%1], 16;" \
        :: "r"(dst), "l"(src) : "memory")
#define CP_COMMIT() asm volatile("cp.async.commit_group;" ::: "memory")
#define CP_WAIT1()  asm volatile("cp.async.wait_group 1;" ::: "memory")
#define CP_WAIT0()  asm volatile("cp.async.wait_group 0;" ::: "memory")

__device__ __forceinline__ void ldsm4(uint32_t& r0, uint32_t& r1,
                                      uint32_t& r2, uint32_t& r3, uint32_t addr) {
    asm volatile("ldmatrix.sync.aligned.m8n8.x4.shared.b16 {%0,%1,%2,%3}, [%4];"
        : "=r"(r0), "=r"(r1), "=r"(r2), "=r"(r3) : "r"(addr));
}
// fp16 MMA
__device__ __forceinline__ void mma16816h(float* c,
    uint32_t a0, uint32_t a1, uint32_t a2, uint32_t a3,
    uint32_t b0, uint32_t b1) {
    asm volatile("mma.sync.aligned.m16n8k16.row.col.f32.f16.f16.f32 "
        "{%0,%1,%2,%3}, {%4,%5,%6,%7}, {%8,%9}, {%0,%1,%2,%3};"
        : "+f"(c[0]), "+f"(c[1]), "+f"(c[2]), "+f"(c[3])
        : "r"(a0), "r"(a1), "r"(a2), "r"(a3), "r"(b0), "r"(b1));
}

// ---------------- scratch (device globals; allocation is forbidden) -------
__device__ __half g_q16[(size_t)BHN*SEQ*HD];    // [bh][s][d]
__device__ __half g_k16[(size_t)BHN*SEQ*HD];
__device__ __half g_vT16[(size_t)BHN*HD*SEQ];   // [bh][d][s]
__device__ __half g_x16[(size_t)MTOT*EMB];      // fp16 x
__device__ __half g_af[(size_t)MTOT*EMB];       // fp16 attn (merged heads)
__device__ __half g_w16[4*512*512];             // fp16 W^T [mat][n][k]
__device__ float g_qland[BHN*64*64];
__device__ float g_kland[BHN*64*64];
__device__ __half g_ql16[BHN*64*64];
__device__ __half g_kl16[BHN*64*64];
__device__ __half g_MfT16[BHN*64*64];           // [bh][d][l]
__device__ float g_K2[BHN*64*64];
__device__ float g_Vinv[BHN*64*64];
__device__ float g_Gpart[(size_t)BHN*NCHUNK*64*64];
__device__ float g_Mpart[BHN*NCHUNK*64];
__device__ float g_Lpart[BHN*NCHUNK*64];
__device__ int   g_denom_i;

// =================== split kernels (fp32 -> fp16) =========================
__global__ __launch_bounds__(256) void split_x(const float* __restrict__ x)
{
    size_t i = (size_t)blockIdx.x * 256 + threadIdx.x;   // float4 index
    float4 v = ((const float4*)x)[i];
    __half2 h0 = __floats2half2_rn(v.x, v.y);
    __half2 h1 = __floats2half2_rn(v.z, v.w);
    uint2 u; u.x = *(uint32_t*)&h0; u.y = *(uint32_t*)&h1;
    ((uint2*)g_x16)[i] = u;
}

__global__ __launch_bounds__(256) void split_w(
    const float* __restrict__ Wq, const float* __restrict__ Wk,
    const float* __restrict__ Wv, const float* __restrict__ Wo)
{
    if (blockIdx.x == 0 && blockIdx.y == 0 && threadIdx.x == 0) g_denom_i = 0;
    const float* src = (blockIdx.y == 0) ? Wq : (blockIdx.y == 1) ? Wk
                     : (blockIdx.y == 2) ? Wv : Wo;
    int n = blockIdx.x;
    size_t obase = ((size_t)blockIdx.y * 512 + n) * 512;
    for (int k = threadIdx.x; k < 512; k += 256) {
        g_w16[obase + k] = __float2half(src[(size_t)k * 512 + n]);
    }
}

// =================== single-term fp16 warp-MMA GEMM =======================
#define SUB_SZ   16384
#define STAGE_SZ (2*SUB_SZ)          // 32KB: A, B (fp16)
#define NSTAGE   3
#define SMEM_TOT (NSTAGE*STAGE_SZ)   // 98304

// mode 0: QKV fused (blockIdx.z = 0:q, 1:k, 2:v); mode 1: output GEMM.
__global__ __launch_bounds__(256, 2) void tc_gemm(
    const float* __restrict__ b0, const float* __restrict__ b1,
    const float* __restrict__ b2, float* __restrict__ out_ext, int mode)
{
    extern __shared__ char smem[];
    uint32_t sb = smem_u32(smem);
    int t = threadIdx.x;
    int wid = t >> 5, lane = t & 31;
    int wm = wid & 3, wn = wid >> 2;   // warp grid 4(M) x 2(N)
    int rowStart = blockIdx.y * 128;
    int colStart = blockIdx.x * 128;

    int out_sel, widx;
    const float* bias;
    float scale;
    if (mode == 0) {
        out_sel = blockIdx.z; widx = blockIdx.z;
        bias = (out_sel == 0) ? b0 : (out_sel == 1) ? b1 : b2;
        scale = (out_sel == 2) ? 1.0f : 0.35355339059327373f;
    } else {
        out_sel = 3; widx = 3; bias = b0; scale = 1.0f;
    }

    const __half* Ag = (mode ? g_af : g_x16) + (size_t)rowStart * 512;
    const __half* Bg = g_w16 + ((size_t)widx * 512 + colStart) * 512;

    float acc[2][8][4];
    #pragma unroll
    for (int mt = 0; mt < 2; mt++)
        #pragma unroll
        for (int nt = 0; nt < 8; nt++)
            #pragma unroll
            for (int q = 0; q < 4; q++) acc[mt][nt][q] = 0.f;

    auto issue = [&](int kt, int buf) {
        const __half* srcs[2] = { Ag + kt * 64, Bg + kt * 64 };
        #pragma unroll
        for (int s2 = 0; s2 < 2; s2++) {
            const char* src = (const char*)srcs[s2];
            uint32_t dstb = sb + buf * STAGE_SZ + s2 * SUB_SZ;
            #pragma unroll
            for (int r = 0; r < 4; r++) {
                int ci = r * 256 + t;
                int row = ci >> 3, c16 = ci & 7;
                const char* s = src + (size_t)row * 1024 + c16 * 16;
                uint32_t d = dstb + SMEM_SWIZZLE_128B(row * 128 + c16 * 16);
                CP_ASYNC16(d, s);
            }
        }
        CP_COMMIT();
    };

    issue(0, 0);
    issue(1, 1);
    for (int kt = 0; kt < 8; kt++) {
        if (kt == 7) { CP_WAIT0(); } else { CP_WAIT1(); }
        __syncthreads();
        if (kt + 2 < 8) issue(kt + 2, (kt + 2) % NSTAGE);

        uint32_t sbb = sb + (kt % NSTAGE) * STAGE_SZ;
        uint32_t aB = sbb, bB = sbb + SUB_SZ;

        #pragma unroll
        for (int ks = 0; ks < 4; ks++) {
            uint32_t a[2][4], b[4][4];
            #pragma unroll
            for (int mt = 0; mt < 2; mt++) {
                int row  = wm * 32 + mt * 16 + (lane & 15);
                int boff = ks * 32 + ((lane >> 4) << 4);
                uint32_t off = SMEM_SWIZZLE_128B(row * 128 + boff);
                ldsm4(a[mt][0], a[mt][1], a[mt][2], a[mt][3], aB + off);
            }
            #pragma unroll
            for (int np = 0; np < 4; np++) {
                int g = lane >> 3, l = lane & 7;
                int row  = wn * 64 + np * 16 + ((g >> 1) << 3) + l;
                int boff = ks * 32 + ((g & 1) << 4);
                uint32_t off = SMEM_SWIZZLE_128B(row * 128 + boff);
                ldsm4(b[np][0], b[np][1], b[np][2], b[np][3], bB + off);
            }
            #pragma unroll
            for (int mt = 0; mt < 2; mt++)
                #pragma unroll
                for (int np = 0; np < 4; np++) {
                    mma16816h(acc[mt][2 * np],     a[mt][0], a[mt][1], a[mt][2], a[mt][3],
                              b[np][0], b[np][1]);
                    mma16816h(acc[mt][2 * np + 1], a[mt][0], a[mt][1], a[mt][2], a[mt][3],
                              b[np][2], b[np][3]);
                }
        }
    }
    __syncthreads();

    // ---- epilogue
    int qrow = lane >> 2, qcol = (lane & 3) * 2;
    #pragma unroll
    for (int mt = 0; mt < 2; mt++) {
        #pragma unroll
        for (int nt = 0; nt < 8; nt++) {
            int col = colStart + wn * 64 + nt * 8 + qcol;
            float bb0 = bias[col], bb1 = bias[col + 1];
            #pragma unroll
            for (int hh = 0; hh < 2; hh++) {
                int row = rowStart + wm * 32 + mt * 16 + qrow + hh * 8;
                float fx = (acc[mt][nt][2 * hh + 0] + bb0) * scale;
                float fy = (acc[mt][nt][2 * hh + 1] + bb1) * scale;
                int b_ = row >> 13, s = row & 8191;
                int h = col >> 6, d = col & 63;
                if (out_sel <= 1) {          // q or k: fp16, head-split
                    size_t o = (((size_t)(b_ * NH + h) * SEQ + s) << 6) + d;
                    __half2 hv = __floats2half2_rn(fx, fy);
                    *(uint32_t*)((out_sel == 0 ? g_q16 : g_k16) + o) = *(uint32_t*)&hv;
                } else if (out_sel == 2) {   // v: transposed fp16 [bh][d][s]
                    size_t base = ((size_t)(b_ * NH + h) * 64 + d) * SEQ + s;
                    g_vT16[base]       = __float2half(fx);
                    g_vT16[base + SEQ] = __float2half(fy);
                } else {                     // output: fp32
                    float2 f; f.x = fx; f.y = fy;
                    *(float2*)(out_ext + (size_t)row * 512 + col) = f;
                }
            }
        }
    }

    // ---- fused landmark means for q/k: this M-tile == one 128-row segment
    if (out_sel <= 1) {
        float* red = (float*)smem;   // 128 floats (stage smem is dead now)
        if (t < 128) red[t] = 0.f;
        __syncthreads();
        #pragma unroll
        for (int nt = 0; nt < 8; nt++) {
            float sx = 0.f, sy = 0.f;
            #pragma unroll
            for (int mt = 0; mt < 2; mt++) {
                sx += acc[mt][nt][0] + acc[mt][nt][2];
                sy += acc[mt][nt][1] + acc[mt][nt][3];
            }
            sx += __shfl_xor_sync(0xFFFFFFFF, sx, 4);
            sx += __shfl_xor_sync(0xFFFFFFFF, sx, 8);
            sx += __shfl_xor_sync(0xFFFFFFFF, sx, 16);
            sy += __shfl_xor_sync(0xFFFFFFFF, sy, 4);
            sy += __shfl_xor_sync(0xFFFFFFFF, sy, 8);
            sy += __shfl_xor_sync(0xFFFFFFFF, sy, 16);
            if ((lane >> 2) == 0) {
                int colr = wn * 64 + nt * 8 + qcol;
                atomicAdd(&red[colr],     sx);
                atomicAdd(&red[colr + 1], sy);
            }
        }
        __syncthreads();
        if (t < 128) {
            int col = colStart + t;
            float mean = (red[t] * (1.f / 128.f) + bias[col]) * scale;
            int b_ = rowStart >> 13;
            int l  = (rowStart & 8191) >> 7;
            int h  = col >> 6, d = col & 63;
            int idx = ((b_ * NH + h) * 64 + l) * 64 + d;
            if (out_sel == 0) {
                g_qland[idx] = mean; g_ql16[idx] = __float2half(mean);
            } else {
                g_kland[idx] = mean; g_kl16[idx] = __float2half(mean);
            }
        }
    }
}

// ---------------- 64x64 matmul helpers ------------------------------------
__device__ __forceinline__ void mm64_4x4(float cr[4][4],
    const float* __restrict__ X, int px,
    const float* __restrict__ Y, int py, int tx, int ty)
{
    #pragma unroll 16
    for (int k = 0; k < 64; k++) {
        float a_[4], b_[4];
        #pragma unroll
        for (int ii = 0; ii < 4; ii++) a_[ii] = X[(ty * 4 + ii) * px + k];
        #pragma unroll
        for (int jj = 0; jj < 4; jj++) b_[jj] = Y[k * py + tx * 4 + jj];
        #pragma unroll
        for (int ii = 0; ii < 4; ii++)
            #pragma unroll
            for (int jj = 0; jj < 4; jj++)
                cr[ii][jj] += a_[ii] * b_[jj];
    }
}
__device__ __forceinline__ void mm64_2x4(float cr[2][4],
    const float* __restrict__ X, int px,
    const float* __restrict__ Y, int py, int tx, int ty)
{
    #pragma unroll 16
    for (int k = 0; k < 64; k++) {
        float a_[2], b_[4];
        #pragma unroll
        for (int ii = 0; ii < 2; ii++) a_[ii] = X[(ty * 2 + ii) * px + k];
        #pragma unroll
        for (int jj = 0; jj < 4; jj++) b_[jj] = Y[k * py + tx * 4 + jj];
        #pragma unroll
        for (int ii = 0; ii < 2; ii++)
            #pragma unroll
            for (int jj = 0; jj < 4; jj++)
                cr[ii][jj] += a_[ii] * b_[jj];
    }
}

// ---------------- kernel_2 softmax + global colsum max (512 thr) ----------
__global__ __launch_bounds__(512) void k2_softmax()
{
    int bh = blockIdx.x, t = threadIdx.x;
    __shared__ float qL[4096];
    __shared__ float kT[64 * 65];
    __shared__ float S[64 * 65];
    const float* qlb = g_qland + bh * 4096;
    const float* klb = g_kland + bh * 4096;
    for (int idx = t; idx < 4096; idx += 512) {
        qL[idx] = qlb[idx];
        int j = idx >> 6, d = idx & 63;
        kT[d * 65 + j] = klb[idx];
    }
    __syncthreads();
    int tx = t & 15, ty = t >> 4;
    float cr[2][4] = {};
    mm64_2x4(cr, qL, 64, kT, 65, tx, ty);
    #pragma unroll
    for (int ii = 0; ii < 2; ii++)
        #pragma unroll
        for (int jj = 0; jj < 4; jj++)
            S[(ty * 2 + ii) * 65 + tx * 4 + jj] = cr[ii][jj];
    __syncthreads();
    {
        int row = t >> 3, c8 = (t & 7) * 8;
        float v[8], mx = -1e30f;
        #pragma unroll
        for (int j = 0; j < 8; j++) { v[j] = S[row * 65 + c8 + j]; mx = fmaxf(mx, v[j]); }
        mx = fmaxf(mx, __shfl_xor_sync(0xFFFFFFFF, mx, 1));
        mx = fmaxf(mx, __shfl_xor_sync(0xFFFFFFFF, mx, 2));
        mx = fmaxf(mx, __shfl_xor_sync(0xFFFFFFFF, mx, 4));
        float sum = 0.f;
        #pragma unroll
        for (int j = 0; j < 8; j++) { v[j] = __expf(v[j] - mx); sum += v[j]; }
        sum += __shfl_xor_sync(0xFFFFFFFF, sum, 1);
        sum += __shfl_xor_sync(0xFFFFFFFF, sum, 2);
        sum += __shfl_xor_sync(0xFFFFFFFF, sum, 4);
        float inv = 1.f / sum;
        #pragma unroll
        for (int j = 0; j < 8; j++) S[row * 65 + c8 + j] = v[j] * inv;
    }
    __syncthreads();
    {
        int col = t >> 3, r8 = (t & 7) * 8;
        float cs = 0.f;
        #pragma unroll
        for (int r = 0; r < 8; r++) cs += S[(r8 + r) * 65 + col];
        cs += __shfl_xor_sync(0xFFFFFFFF, cs, 1);
        cs += __shfl_xor_sync(0xFFFFFFFF, cs, 2);
        cs += __shfl_xor_sync(0xFFFFFFFF, cs, 4);
        if ((t & 7) == 0) atomicMax(&g_denom_i, __float_as_int(cs));
    }
    float* ko = g_K2 + bh * 4096;
    for (int idx = t; idx < 4096; idx += 512) {
        int i = idx >> 6, j = idx & 63;
        ko[idx] = S[i * 65 + j];
    }
}

// ---------------- Newton-Schulz pseudo-inverse (256 thr, 4x4) -------------
__global__ __launch_bounds__(256) void newton_inv()
{
    int bh = blockIdx.x, t = threadIdx.x;
    extern __shared__ float sm[];
    float* Kd = sm;
    float* V  = Kd + 4096;
    float* C  = V  + 4096;
    float* M1 = C  + 4096;
    float* M2 = M1 + 4096;
    const float* kb = g_K2 + bh * 4096;
    for (int idx = t; idx < 4096; idx += 256) Kd[idx] = kb[idx];
    float denom = __int_as_float(g_denom_i);
    __syncthreads();
    float inv = 1.f / denom;
    for (int idx = t; idx < 4096; idx += 256) {
        int i = idx >> 6, j = idx & 63;
        V[idx] = Kd[j * 64 + i] * inv;
    }
    __syncthreads();
    int tx = t & 15, ty = t >> 4;
    for (int it = 0; it < 6; it++) {
        { float cr[4][4] = {}; mm64_4x4(cr, Kd, 64, V, 64, tx, ty);
          #pragma unroll
          for (int ii = 0; ii < 4; ii++) for (int jj = 0; jj < 4; jj++)
              C[(ty*4+ii)*64 + tx*4+jj] = cr[ii][jj]; }
        __syncthreads();
        { float cr[4][4] = {}; mm64_4x4(cr, C, 64, C, 64, tx, ty);
          #pragma unroll
          for (int ii = 0; ii < 4; ii++) for (int jj = 0; jj < 4; jj++) {
              int o = (ty*4+ii)*64 + tx*4+jj;
              M1[o] = 7.f * C[o] - cr[ii][jj]; } }
        __syncthreads();
        { float cr[4][4] = {}; mm64_4x4(cr, C, 64, M1, 64, tx, ty);
          #pragma unroll
          for (int ii = 0; ii < 4; ii++) for (int jj = 0; jj < 4; jj++) {
              int o = (ty*4+ii)*64 + tx*4+jj;
              M2[o] = 15.f * C[o] - cr[ii][jj]; } }
        __syncthreads();
        { float cr[4][4] = {}; mm64_4x4(cr, V, 64, M2, 64, tx, ty);
          #pragma unroll
          for (int ii = 0; ii < 4; ii++) for (int jj = 0; jj < 4; jj++) {
              int o = (ty*4+ii)*64 + tx*4+jj;
              M1[o] = 3.25f * V[o] - 0.25f * cr[ii][jj]; } }
        __syncthreads();
        for (int idx = t; idx < 4096; idx += 256) V[idx] = M1[idx];
        __syncthreads();
    }
    float* vo = g_Vinv + bh * 4096;
    for (int idx = t; idx < 4096; idx += 256) vo[idx] = V[idx];
}

// ---------------- flash kernel_3 @ v : fp16 MMA version -------------------
#define FL_Q    0
#define FL_BUF  8192           // buf b at FL_BUF + b*16384; sub: k16, vT16 (8KB each)
#define FL_SMEM 40960

__global__ __launch_bounds__(128, 3) void flash_k3v_mma()
{
    extern __shared__ char fs[];
    uint32_t sb = smem_u32(fs);
    const int t = threadIdx.x, w = t >> 5, lane = t & 31;
    const int chunk = blockIdx.x, bhead = blockIdx.y;

    {
        const __half* qh = g_ql16 + bhead * 4096;
        #pragma unroll
        for (int i = 0; i < 4; i++) {
            int ci = i * 128 + t;
            int row = ci >> 3, c16 = ci & 7;
            uint32_t sw = SMEM_SWIZZLE_128B(row * 128 + c16 * 16);
            *(uint4*)(fs + FL_Q + sw) = *(const uint4*)(qh + row * 64 + c16 * 8);
        }
    }
    __syncthreads();

    uint32_t ah[4][4];
    #pragma unroll
    for (int ks = 0; ks < 4; ks++) {
        int row  = w * 16 + (lane & 15);
        int boff = ks * 32 + ((lane >> 4) << 4);
        uint32_t off = SMEM_SWIZZLE_128B(row * 128 + boff);
        ldsm4(ah[ks][0], ah[ks][1], ah[ks][2], ah[ks][3], sb + FL_Q + off);
    }

    auto issue = [&](int sub, int b) {
        int s0 = chunk * CHUNK + sub * 64;
        const __half* srcs[2] = {
            g_k16  + ((size_t)bhead * SEQ + s0) * 64,
            g_vT16 + ((size_t)bhead * 64) * SEQ + s0 };
        #pragma unroll
        for (int s2 = 0; s2 < 2; s2++) {
            size_t rs = (s2 == 0) ? 64 : SEQ;
            const char* src = (const char*)srcs[s2];
            uint32_t dstb = sb + FL_BUF + b * 16384 + s2 * 8192;
            #pragma unroll
            for (int r = 0; r < 4; r++) {
                int ci = r * 128 + t;
                int row = ci >> 3, c16 = ci & 7;
                const char* s = src + (row * rs + c16 * 8) * 2;
                CP_ASYNC16(dstb + SMEM_SWIZZLE_128B(row * 128 + c16 * 16), s);
            }
        }
        CP_COMMIT();
    };

    float mA = -1e30f, mB = -1e30f, lA = 0.f, lB = 0.f;
    float o[8][4];
    #pragma unroll
    for (int nt = 0; nt < 8; nt++)
        #pragma unroll
        for (int q = 0; q < 4; q++) o[nt][q] = 0.f;

    issue(0, 0);
    for (int sub = 0; sub < 8; sub++) {
        int buf = sub & 1;
        if (sub + 1 < 8) { issue(sub + 1, buf ^ 1); CP_WAIT1(); }
        else            { CP_WAIT0(); }
        __syncthreads();

        uint32_t khb = sb + FL_BUF + buf * 16384;
        uint32_t vhb = khb + 8192;

        float c[8][4];
        #pragma unroll
        for (int nt = 0; nt < 8; nt++)
            #pragma unroll
            for (int q = 0; q < 4; q++) c[nt][q] = 0.f;

        #pragma unroll
        for (int ks = 0; ks < 4; ks++) {
            #pragma unroll
            for (int np = 0; np < 4; np++) {
                int g = lane >> 3, l = lane & 7;
                int row  = np * 16 + ((g >> 1) << 3) + l;
                int boff = ks * 32 + ((g & 1) << 4);
                uint32_t off = SMEM_SWIZZLE_128B(row * 128 + boff);
                uint32_t kb[4];
                ldsm4(kb[0], kb[1], kb[2], kb[3], khb + off);
                mma16816h(c[2 * np],     ah[ks][0], ah[ks][1], ah[ks][2], ah[ks][3], kb[0], kb[1]);
                mma16816h(c[2 * np + 1], ah[ks][0], ah[ks][1], ah[ks][2], ah[ks][3], kb[2], kb[3]);
            }
        }

        float mxA = -1e30f, mxB = -1e30f;
        #pragma unroll
        for (int nt = 0; nt < 8; nt++) {
            mxA = fmaxf(mxA, fmaxf(c[nt][0], c[nt][1]));
            mxB = fmaxf(mxB, fmaxf(c[nt][2], c[nt][3]));
        }
        mxA = fmaxf(mxA, __shfl_xor_sync(0xFFFFFFFF, mxA, 1));
        mxA = fmaxf(mxA, __shfl_xor_sync(0xFFFFFFFF, mxA, 2));
        mxB = fmaxf(mxB, __shfl_xor_sync(0xFFFFFFFF, mxB, 1));
        mxB = fmaxf(mxB, __shfl_xor_sync(0xFFFFFFFF, mxB, 2));
        float mnA = fmaxf(mA, mxA), mnB = fmaxf(mB, mxB);
        float fA = __expf(mA - mnA), fB = __expf(mB - mnB);
        float sumA = 0.f, sumB = 0.f;
        #pragma unroll
        for (int nt = 0; nt < 8; nt++) {
            c[nt][0] = __expf(c[nt][0] - mnA); sumA += c[nt][0];
            c[nt][1] = __expf(c[nt][1] - mnA); sumA += c[nt][1];
            c[nt][2] = __expf(c[nt][2] - mnB); sumB += c[nt][2];
            c[nt][3] = __expf(c[nt][3] - mnB); sumB += c[nt][3];
        }
        sumA += __shfl_xor_sync(0xFFFFFFFF, sumA, 1);
        sumA += __shfl_xor_sync(0xFFFFFFFF, sumA, 2);
        sumB += __shfl_xor_sync(0xFFFFFFFF, sumB, 1);
        sumB += __shfl_xor_sync(0xFFFFFFFF, sumB, 2);
        lA = lA * fA + sumA; lB = lB * fB + sumB;
        mA = mnA; mB = mnB;
        #pragma unroll
        for (int nt = 0; nt < 8; nt++) {
            o[nt][0] *= fA; o[nt][1] *= fA;
            o[nt][2] *= fB; o[nt][3] *= fB;
        }

        #pragma unroll
        for (int kt = 0; kt < 4; kt++) {
            uint32_t pa[4];
            __half2 p0 = __floats2half2_rn(c[2*kt][0],   c[2*kt][1]);
            __half2 p1 = __floats2half2_rn(c[2*kt][2],   c[2*kt][3]);
            __half2 p2 = __floats2half2_rn(c[2*kt+1][0], c[2*kt+1][1]);
            __half2 p3 = __floats2half2_rn(c[2*kt+1][2], c[2*kt+1][3]);
            pa[0] = *(uint32_t*)&p0; pa[1] = *(uint32_t*)&p1;
            pa[2] = *(uint32_t*)&p2; pa[3] = *(uint32_t*)&p3;
            #pragma unroll
            for (int np = 0; np < 4; np++) {
                int g = lane >> 3, l = lane & 7;
                int row  = np * 16 + ((g >> 1) << 3) + l;
                int boff = kt * 32 + ((g & 1) << 4);
                uint32_t off = SMEM_SWIZZLE_128B(row * 128 + boff);
                uint32_t vh[4];
                ldsm4(vh[0], vh[1], vh[2], vh[3], vhb + off);
                mma16816h(o[2 * np],     pa[0], pa[1], pa[2], pa[3], vh[0], vh[1]);
                mma16816h(o[2 * np + 1], pa[0], pa[1], pa[2], pa[3], vh[2], vh[3]);
            }
        }
        __syncthreads();
    }

    float* gp = g_Gpart + (size_t)(bhead * NCHUNK + chunk) * 4096;
    int rA = w * 16 + (lane >> 2), rB = rA + 8;
    #pragma unroll
    for (int nt = 0; nt < 8; nt++) {
        int col = (nt >> 1) * 16 + (nt & 1) * 8 + (lane & 3) * 2;
        *(float2*)(gp + rA * 64 + col) = make_float2(o[nt][0], o[nt][1]);
        *(float2*)(gp + rB * 64 + col) = make_float2(o[nt][2], o[nt][3]);
    }
    if ((lane & 3) == 0) {
        int base = (bhead * NCHUNK + chunk) * 64;
        g_Mpart[base + rA] = mA; g_Mpart[base + rB] = mB;
        g_Lpart[base + rA] = lA; g_Lpart[base + rB] = lB;
    }
}

// ------- fused: merge partials -> G3v, then Mf = Vinv @ G3v (256 thr) -----
__global__ __launch_bounds__(256) void apply_inv()
{
    int bh = blockIdx.x, t = threadIdx.x;
    __shared__ float A[4096], B[4096];
    __shared__ float mrow[64], zinv[64];
    __shared__ float wgt[NCHUNK * 64];

    const float* va = g_Vinv + bh * 4096;
    for (int idx = t; idx < 4096; idx += 256) A[idx] = va[idx];

    if (t < 64) {
        float m = -1e30f;
        for (int c = 0; c < NCHUNK; c++)
            m = fmaxf(m, g_Mpart[(bh * NCHUNK + c) * 64 + t]);
        float z = 0.f;
        for (int c = 0; c < NCHUNK; c++)
            z += __expf(g_Mpart[(bh * NCHUNK + c) * 64 + t] - m) *
                 g_Lpart[(bh * NCHUNK + c) * 64 + t];
        mrow[t] = m; zinv[t] = 1.f / z;
    }
    __syncthreads();
    for (int idx = t; idx < NCHUNK * 64; idx += 256) {
        int c = idx >> 6, i = idx & 63;
        wgt[idx] = __expf(g_Mpart[(bh * NCHUNK + c) * 64 + i] - mrow[i]);
    }
    __syncthreads();
    for (int idx = t; idx < 4096; idx += 256) {
        int i = idx >> 6, d = idx & 63;
        float accv = 0.f;
        #pragma unroll 4
        for (int c = 0; c < NCHUNK; c++)
            accv += wgt[c * 64 + i] *
                    g_Gpart[((size_t)(bh * NCHUNK + c)) * 4096 + i * 64 + d];
        B[idx] = accv * zinv[i];
    }
    __syncthreads();

    int tx = t & 15, ty = t >> 4;
    float cr[4][4] = {};
    mm64_4x4(cr, A, 64, B, 64, tx, ty);
    #pragma unroll
    for (int ii = 0; ii < 4; ii++)
        #pragma unroll
        for (int jj = 0; jj < 4; jj++) {
            int i = ty * 4 + ii, j = tx * 4 + jj;
            g_MfT16[bh * 4096 + j * 64 + i] = __float2half(cr[ii][jj]);
        }
}

// ---------------- kernel_1 softmax + @Mf : fp16 MMA version ---------------
#define K1_Q    0
#define K1_K    8192
#define K1_M    16384
#define K1_SMEM 24576

__global__ __launch_bounds__(128, 4) void k1_apply_mma()
{
    extern __shared__ char fs[];
    uint32_t sb = smem_u32(fs);
    const int t = threadIdx.x, w = t >> 5, lane = t & 31;
    const int st = blockIdx.x, bhead = blockIdx.y;

    {
        const __half* srcs[3] = {
            g_q16 + ((size_t)bhead * SEQ + st * 64) * 64,
            g_kl16 + bhead * 4096,
            g_MfT16 + bhead * 4096 };
        #pragma unroll
        for (int s3 = 0; s3 < 3; s3++) {
            const __half* src = srcs[s3];
            int dstb = s3 * 8192;
            #pragma unroll
            for (int i = 0; i < 4; i++) {
                int ci = i * 128 + t;
                int row = ci >> 3, c16 = ci & 7;
                uint32_t sw = SMEM_SWIZZLE_128B(row * 128 + c16 * 16);
                *(uint4*)(fs + dstb + sw) = *(const uint4*)(src + row * 64 + c16 * 8);
            }
        }
    }
    __syncthreads();

    float c[8][4];
    #pragma unroll
    for (int nt = 0; nt < 8; nt++)
        #pragma unroll
        for (int q = 0; q < 4; q++) c[nt][q] = 0.f;

    #pragma unroll
    for (int ks = 0; ks < 4; ks++) {
        uint32_t a[4];
        {
            int row  = w * 16 + (lane & 15);
            int boff = ks * 32 + ((lane >> 4) << 4);
            uint32_t off = SMEM_SWIZZLE_128B(row * 128 + boff);
            ldsm4(a[0], a[1], a[2], a[3], sb + K1_Q + off);
        }
        #pragma unroll
        for (int np = 0; np < 4; np++) {
            int g = lane >> 3, l = lane & 7;
            int row  = np * 16 + ((g >> 1) << 3) + l;
            int boff = ks * 32 + ((g & 1) << 4);
            uint32_t off = SMEM_SWIZZLE_128B(row * 128 + boff);
            uint32_t kb[4];
            ldsm4(kb[0], kb[1], kb[2], kb[3], sb + K1_K + off);
            mma16816h(c[2 * np],     a[0], a[1], a[2], a[3], kb[0], kb[1]);
            mma16816h(c[2 * np + 1], a[0], a[1], a[2], a[3], kb[2], kb[3]);
        }
    }

    float mxA = -1e30f, mxB = -1e30f;
    #pragma unroll
    for (int nt = 0; nt < 8; nt++) {
        mxA = fmaxf(mxA, fmaxf(c[nt][0], c[nt][1]));
        mxB = fmaxf(mxB, fmaxf(c[nt][2], c[nt][3]));
    }
    mxA = fmaxf(mxA, __shfl_xor_sync(0xFFFFFFFF, mxA, 1));
    mxA = fmaxf(mxA, __shfl_xor_sync(0xFFFFFFFF, mxA, 2));
    mxB = fmaxf(mxB, __shfl_xor_sync(0xFFFFFFFF, mxB, 1));
    mxB = fmaxf(mxB, __shfl_xor_sync(0xFFFFFFFF, mxB, 2));
    float sumA = 0.f, sumB = 0.f;
    #pragma unroll
    for (int nt = 0; nt < 8; nt++) {
        c[nt][0] = __expf(c[nt][0] - mxA); sumA += c[nt][0];
        c[nt][1] = __expf(c[nt][1] - mxA); sumA += c[nt][1];
        c[nt][2] = __expf(c[nt][2] - mxB); sumB += c[nt][2];
        c[nt][3] = __expf(c[nt][3] - mxB); sumB += c[nt][3];
    }
    sumA += __shfl_xor_sync(0xFFFFFFFF, sumA, 1);
    sumA += __shfl_xor_sync(0xFFFFFFFF, sumA, 2);
    sumB += __shfl_xor_sync(0xFFFFFFFF, sumB, 1);
    sumB += __shfl_xor_sync(0xFFFFFFFF, sumB, 2);
    float iA = 1.f / sumA, iB = 1.f / sumB;
    #pragma unroll
    for (int nt = 0; nt < 8; nt++) {
        c[nt][0] *= iA; c[nt][1] *= iA;
        c[nt][2] *= iB; c[nt][3] *= iB;
    }

    float o[8][4];
    #pragma unroll
    for (int nt = 0; nt < 8; nt++)
        #pragma unroll
        for (int q = 0; q < 4; q++) o[nt][q] = 0.f;

    #pragma unroll
    for (int kt = 0; kt < 4; kt++) {
        uint32_t pa[4];
        __half2 p0 = __floats2half2_rn(c[2*kt][0],   c[2*kt][1]);
        __half2 p1 = __floats2half2_rn(c[2*kt][2],   c[2*kt][3]);
        __half2 p2 = __floats2half2_rn(c[2*kt+1][0], c[2*kt+1][1]);
        __half2 p3 = __floats2half2_rn(c[2*kt+1][2], c[2*kt+1][3]);
        pa[0] = *(uint32_t*)&p0; pa[1] = *(uint32_t*)&p1;
        pa[2] = *(uint32_t*)&p2; pa[3] = *(uint32_t*)&p3;
        #pragma unroll
        for (int np = 0; np < 4; np++) {
            int g = lane >> 3, l = lane & 7;
            int row  = np * 16 + ((g >> 1) << 3) + l;
            int boff = kt * 32 + ((g & 1) << 4);
            uint32_t off = SMEM_SWIZZLE_128B(row * 128 + boff);
            uint32_t mh[4];
            ldsm4(mh[0], mh[1], mh[2], mh[3], sb + K1_M + off);
            mma16816h(o[2 * np],     pa[0], pa[1], pa[2], pa[3], mh[0], mh[1]);
            mma16816h(o[2 * np + 1], pa[0], pa[1], pa[2], pa[3], mh[2], mh[3]);
        }
    }

    // ---- epilogue: write merged-head fp16 for the output GEMM
    int b_ = bhead >> 3, h = bhead & 7;
    int sA = st * 64 + w * 16 + (lane >> 2), sB = sA + 8;
    #pragma unroll
    for (int nt = 0; nt < 8; nt++) {
        int col = (nt >> 1) * 16 + (nt & 1) * 8 + (lane & 3) * 2;
        size_t oA = ((size_t)(b_ * SEQ + sA)) * 512 + h * 64 + col;
        __half2 hA = __floats2half2_rn(o[nt][0], o[nt][1]);
        *(uint32_t*)(g_af + oA) = *(uint32_t*)&hA;
        size_t oB = ((size_t)(b_ * SEQ + sB)) * 512 + h * 64 + col;
        __half2 hB = __floats2half2_rn(o[nt][2], o[nt][3]);
        *(uint32_t*)(g_af + oB) = *(uint32_t*)&hB;
    }
}

// ---------------- launch --------------------------------------------------
extern "C" void kernel_launch(void* const* d_in, const int* in_sizes, int n_in,
                              void* d_out, int out_size)
{
    const float* x  = (const float*)d_in[0];
    const float* Wq = (const float*)d_in[1];
    const float* bq = (const float*)d_in[2];
    const float* Wk = (const float*)d_in[3];
    const float* bk = (const float*)d_in[4];
    const float* Wv = (const float*)d_in[5];
    const float* bv = (const float*)d_in[6];
    const float* Wo = (const float*)d_in[7];
    const float* bo = (const float*)d_in[8];
    float* out = (float*)d_out;

    // one-time host-side resources (no device memory involved)
    static cudaStream_t s2 = nullptr;
    static cudaEvent_t evFork = nullptr, evJoin = nullptr;
    if (s2 == nullptr) {
        cudaStreamCreateWithFlags(&s2, cudaStreamNonBlocking);
        cudaEventCreateWithFlags(&evFork, cudaEventDisableTiming);
        cudaEventCreateWithFlags(&evJoin, cudaEventDisableTiming);
        cudaFuncSetAttribute(tc_gemm,       cudaFuncAttributeMaxDynamicSharedMemorySize, SMEM_TOT);
        cudaFuncSetAttribute(newton_inv,    cudaFuncAttributeMaxDynamicSharedMemorySize, 5 * 4096 * 4);
        cudaFuncSetAttribute(flash_k3v_mma, cudaFuncAttributeMaxDynamicSharedMemorySize, FL_SMEM);
        cudaFuncSetAttribute(k1_apply_mma,  cudaFuncAttributeMaxDynamicSharedMemorySize, K1_SMEM);
    }

    split_w<<<dim3(512, 4), 256>>>(Wq, Wk, Wv, Wo);
    split_x<<<(MTOT * EMB / 4) / 256, 256>>>(x);

    tc_gemm<<<dim3(4, 256, 3), 256, SMEM_TOT>>>(bq, bk, bv, nullptr, 0); // QKV + landmarks

    // fork: k2 -> newton on side stream, flash on main stream (independent)
    cudaEventRecord(evFork, 0);
    cudaStreamWaitEvent(s2, evFork, 0);
    k2_softmax<<<BHN, 512, 0, s2>>>();
    newton_inv<<<BHN, 256, 5 * 4096 * 4, s2>>>();
    cudaEventRecord(evJoin, s2);

    flash_k3v_mma<<<dim3(NCHUNK, BHN), 128, FL_SMEM>>>();

    // join: apply_inv needs both newton (side) and flash (main)
    cudaStreamWaitEvent(0, evJoin, 0);
    apply_inv<<<BHN, 256>>>();
    k1_apply_mma<<<dim3(SEQ / 64, BHN), 128, K1_SMEM>>>();

    tc_gemm<<<dim3(4, 256, 1), 256, SMEM_TOT>>>(bo, nullptr, nullptr, out, 1);
}